// round 1
// baseline (speedup 1.0000x reference)
#include <cuda_runtime.h>
#include <cuda_bf16.h>

// One CTA per 64x64 image. 256 threads.
// Thread t handles row r = t>>2, 16 consecutive columns starting at (t&3)*16.
// Conv uses a register sliding column window: 3 LDS per output pixel.

#define IMG_PIX 4096
#define NUM_IMG 2048

__device__ __forceinline__ void load_col(const float* __restrict__ s, int r, int cc, float* v) {
    if ((unsigned)cc < 64u) {
        v[0] = (r > 0)  ? s[((r - 1) << 6) + cc] : 0.0f;
        v[1] =            s[(r << 6) + cc];
        v[2] = (r < 63) ? s[((r + 1) << 6) + cc] : 0.0f;
    } else {
        v[0] = 0.0f; v[1] = 0.0f; v[2] = 0.0f;
    }
}

__global__ __launch_bounds__(256, 1)
void sobel_norm_kernel(const float* __restrict__ in,
                       const float* __restrict__ w,
                       const float* __restrict__ wf,
                       const float* __restrict__ scale_p,
                       float* __restrict__ out) {
    __shared__ float s[IMG_PIX];
    __shared__ float smin[8];
    __shared__ float smax[8];

    const int img = blockIdx.x;
    const int tid = threadIdx.x;

    // --- Stage image into smem (coalesced float4) ---
    const float4* __restrict__ in4 = reinterpret_cast<const float4*>(in + (size_t)img * IMG_PIX);
    float4* s4 = reinterpret_cast<float4*>(s);
#pragma unroll
    for (int i = 0; i < 4; i++)
        s4[tid + i * 256] = in4[tid + i * 256];

    // --- Build 3x3 kernel in registers (cheap; hits L2/const) ---
    const float f = fminf(fmaxf(wf[0], 1.0f), 255.0f);
    float wr[9];
#pragma unroll
    for (int i = 0; i < 9; i++)
        wr[i] = fminf(fmaxf(w[i], -1.0f), 1.0f) * f;
    const float sc = scale_p[0];

    __syncthreads();

    const int r  = tid >> 2;          // 0..63
    const int c0 = (tid & 3) << 4;    // 0,16,32,48

    // Sliding window of 3 image columns x 3 rows
    float col0[3], col1[3], col2[3];
    load_col(s, r, c0 - 1, col0);
    load_col(s, r, c0,     col1);

    float g[16];
    float gmn = 3.4e38f;
    float gmx = 0.0f;   // g >= 0 always

#pragma unroll
    for (int i = 0; i < 16; i++) {
        load_col(s, r, c0 + 1 + i, col2);
        float gx = 0.0f, gy = 0.0f;
#pragma unroll
        for (int dr = 0; dr < 3; dr++) {
            // gx: kernel wr, cross-correlation (XLA conv does not flip)
            gx = fmaf(wr[dr * 3 + 0], col0[dr], gx);
            gx = fmaf(wr[dr * 3 + 1], col1[dr], gx);
            gx = fmaf(wr[dr * 3 + 2], col2[dr], gx);
            // gy: kernel wr^T
            gy = fmaf(wr[0 * 3 + dr], col0[dr], gy);
            gy = fmaf(wr[1 * 3 + dr], col1[dr], gy);
            gy = fmaf(wr[2 * 3 + dr], col2[dr], gy);
        }
        const float gv = fabsf(gx) + fabsf(gy);
        g[i] = gv;
        gmn = fminf(gmn, gv);
        gmx = fmaxf(gmx, gv);
#pragma unroll
        for (int d = 0; d < 3; d++) { col0[d] = col1[d]; col1[d] = col2[d]; }
    }

    // --- Block min/max reduction ---
#pragma unroll
    for (int o = 16; o; o >>= 1) {
        gmn = fminf(gmn, __shfl_xor_sync(0xffffffffu, gmn, o));
        gmx = fmaxf(gmx, __shfl_xor_sync(0xffffffffu, gmx, o));
    }
    if ((tid & 31) == 0) { smin[tid >> 5] = gmn; smax[tid >> 5] = gmx; }
    __syncthreads();
    gmn = smin[0]; gmx = smax[0];
#pragma unroll
    for (int i = 1; i < 8; i++) {
        gmn = fminf(gmn, smin[i]);
        gmx = fmaxf(gmx, smax[i]);
    }

    const float dx = fmaxf(gmx - gmn, 1.0f);

    // --- Normalize + floor + scale, float4 stores ---
    float* __restrict__ op = out + (size_t)img * IMG_PIX + (r << 6) + c0;
#pragma unroll
    for (int i = 0; i < 16; i += 4) {
        float4 o4;
        o4.x = floorf((g[i + 0] - gmn) / dx * 255.0f) / sc;
        o4.y = floorf((g[i + 1] - gmn) / dx * 255.0f) / sc;
        o4.z = floorf((g[i + 2] - gmn) / dx * 255.0f) / sc;
        o4.w = floorf((g[i + 3] - gmn) / dx * 255.0f) / sc;
        reinterpret_cast<float4*>(op)[i >> 2] = o4;
    }
}

extern "C" void kernel_launch(void* const* d_in, const int* in_sizes, int n_in,
                              void* d_out, int out_size) {
    const float* in      = (const float*)d_in[0];  // (2048,1,64,64) fp32
    const float* w       = (const float*)d_in[1];  // (1,9) fp32
    const float* wf      = (const float*)d_in[2];  // (1,) fp32
    const float* scale_p = (const float*)d_in[3];  // (1,1) fp32
    float* out = (float*)d_out;                    // (1,2048,1,64,64) fp32
    (void)in_sizes; (void)n_in; (void)out_size;

    sobel_norm_kernel<<<NUM_IMG, 256>>>(in, w, wf, scale_p, out);
}

// round 2
// speedup vs baseline: 2.8906x; 2.8906x over previous
#include <cuda_runtime.h>
#include <cuda_bf16.h>

// One CTA per 64x64 image. 256 threads.
// Thread t owns column c = t&63 and rows [rb*16, rb*16+16), rb = t>>6.
// 3x3 window slides VERTICALLY; every LDS is lane-consecutive -> conflict-free.

#define IMG_PIX 4096
#define NUM_IMG 2048

__device__ __forceinline__ void load3(const float* __restrict__ s, int row, int c,
                                      float& l, float& m, float& r) {
    if ((unsigned)row < 64u) {
        const float* rp = s + (row << 6);
        m = rp[c];
        l = (c > 0)  ? rp[c - 1] : 0.0f;
        r = (c < 63) ? rp[c + 1] : 0.0f;
    } else {
        l = 0.0f; m = 0.0f; r = 0.0f;
    }
}

__global__ __launch_bounds__(256)
void sobel_norm_kernel(const float* __restrict__ in,
                       const float* __restrict__ w,
                       const float* __restrict__ wf,
                       const float* __restrict__ scale_p,
                       float* __restrict__ out) {
    __shared__ float s[IMG_PIX];
    __shared__ float smin[8];
    __shared__ float smax[8];

    const int img = blockIdx.x;
    const int tid = threadIdx.x;

    // --- Stage image into smem (coalesced float4) ---
    const float4* __restrict__ in4 = reinterpret_cast<const float4*>(in + (size_t)img * IMG_PIX);
    float4* s4 = reinterpret_cast<float4*>(s);
#pragma unroll
    for (int i = 0; i < 4; i++)
        s4[tid + i * 256] = in4[tid + i * 256];

    // --- Build 3x3 kernel in registers ---
    const float f = fminf(fmaxf(wf[0], 1.0f), 255.0f);
    float wr[9];
#pragma unroll
    for (int i = 0; i < 9; i++)
        wr[i] = fminf(fmaxf(w[i], -1.0f), 1.0f) * f;
    const float sc = scale_p[0];

    __syncthreads();

    const int c  = tid & 63;          // column 0..63
    const int r0 = (tid >> 6) << 4;   // row block start: 0,16,32,48

    // Vertical sliding window: top / mid / bot rows, each (left,center,right)
    float tl, tm, tr, ml, mm, mr, bl, bm, br;
    load3(s, r0 - 1, c, tl, tm, tr);
    load3(s, r0,     c, ml, mm, mr);

    float g[16];
    float gmn = 3.4e38f;
    float gmx = 0.0f;   // g >= 0 always

#pragma unroll
    for (int i = 0; i < 16; i++) {
        load3(s, r0 + i + 1, c, bl, bm, br);
        // gx: kernel wr (cross-correlation), gy: wr^T
        float gx, gy;
        gx = wr[0] * tl;            gy = wr[0] * tl;
        gx = fmaf(wr[1], tm, gx);   gy = fmaf(wr[3], tm, gy);
        gx = fmaf(wr[2], tr, gx);   gy = fmaf(wr[6], tr, gy);
        gx = fmaf(wr[3], ml, gx);   gy = fmaf(wr[1], ml, gy);
        gx = fmaf(wr[4], mm, gx);   gy = fmaf(wr[4], mm, gy);
        gx = fmaf(wr[5], mr, gx);   gy = fmaf(wr[7], mr, gy);
        gx = fmaf(wr[6], bl, gx);   gy = fmaf(wr[2], bl, gy);
        gx = fmaf(wr[7], bm, gx);   gy = fmaf(wr[5], bm, gy);
        gx = fmaf(wr[8], br, gx);   gy = fmaf(wr[8], br, gy);

        const float gv = fabsf(gx) + fabsf(gy);
        g[i] = gv;
        gmn = fminf(gmn, gv);
        gmx = fmaxf(gmx, gv);

        tl = ml; tm = mm; tr = mr;
        ml = bl; mm = bm; mr = br;
    }

    // --- Block min/max reduction ---
#pragma unroll
    for (int o = 16; o; o >>= 1) {
        gmn = fminf(gmn, __shfl_xor_sync(0xffffffffu, gmn, o));
        gmx = fmaxf(gmx, __shfl_xor_sync(0xffffffffu, gmx, o));
    }
    if ((tid & 31) == 0) { smin[tid >> 5] = gmn; smax[tid >> 5] = gmx; }
    __syncthreads();
    gmn = smin[0]; gmx = smax[0];
#pragma unroll
    for (int i = 1; i < 8; i++) {
        gmn = fminf(gmn, smin[i]);
        gmx = fmaxf(gmx, smax[i]);
    }

    const float dx  = fmaxf(gmx - gmn, 1.0f);
    const float mul = 255.0f / dx;
    const float inv_sc = 1.0f / sc;

    // --- Normalize + floor + scale; lane=column -> coalesced stores ---
    float* __restrict__ op = out + (size_t)img * IMG_PIX + (r0 << 6) + c;
#pragma unroll
    for (int i = 0; i < 16; i++)
        op[i << 6] = floorf((g[i] - gmn) * mul) * inv_sc;
}

extern "C" void kernel_launch(void* const* d_in, const int* in_sizes, int n_in,
                              void* d_out, int out_size) {
    const float* in      = (const float*)d_in[0];  // (2048,1,64,64) fp32
    const float* w       = (const float*)d_in[1];  // (1,9) fp32
    const float* wf      = (const float*)d_in[2];  // (1,) fp32
    const float* scale_p = (const float*)d_in[3];  // (1,1) fp32
    float* out = (float*)d_out;                    // (1,2048,1,64,64) fp32
    (void)in_sizes; (void)n_in; (void)out_size;

    sobel_norm_kernel<<<NUM_IMG, 256>>>(in, w, wf, scale_p, out);
}

// round 3
// speedup vs baseline: 3.4615x; 1.1975x over previous
#include <cuda_runtime.h>
#include <cuda_bf16.h>

// One CTA per 64x64 image, 256 threads.
// Thread t: col quad q = t&15 (cols 4q..4q+3), row block rb = t>>4 (rows 4rb..4rb+3).
// Image read directly from global (L2-resident) as float4; L/R halo via warp shuffle.
// Conv uses S/D split: |gx|+|gy| == max(|conv(S)|, |conv(D)|), S=wr+wr^T, D=wr-wr^T.

#define FULL 0xffffffffu
#define NUM_IMG 2048

__global__ __launch_bounds__(256)
void sobel_norm_kernel(const float* __restrict__ in,
                       const float* __restrict__ w,
                       const float* __restrict__ wf,
                       const float* __restrict__ scale_p,
                       float* __restrict__ out) {
    __shared__ float smin[8];
    __shared__ float smax[8];

    const int img = blockIdx.x;
    const int tid = threadIdx.x;
    const int q   = tid & 15;        // col quad 0..15
    const int rb  = tid >> 4;        // row block 0..15
    const int r0  = rb << 2;         // first output row
    const int c0  = q << 2;          // first output col

    // --- weights: clip, scale, build sym/antisym kernels ---
    const float f = fminf(fmaxf(wf[0], 1.0f), 255.0f);
    float wr[9];
#pragma unroll
    for (int i = 0; i < 9; i++)
        wr[i] = fminf(fmaxf(__ldg(w + i), -1.0f), 1.0f) * f;
    const float s00 = wr[0] + wr[0];
    const float s11 = wr[4] + wr[4];
    const float s22 = wr[8] + wr[8];
    const float s01 = wr[1] + wr[3];
    const float s02 = wr[2] + wr[6];
    const float s12 = wr[5] + wr[7];
    const float d01 = wr[1] - wr[3];
    const float d02 = wr[2] - wr[6];
    const float d12 = wr[5] - wr[7];

    const float* __restrict__ base = in + (size_t)img * 4096 + c0;

    // Sliding 3-row window; each row is 6 floats: cols c0-1 .. c0+4.
    float W[3][6];

    auto load_row = [&](int j, float* V) {
        float4 m = make_float4(0.f, 0.f, 0.f, 0.f);
        if ((unsigned)j < 64u)
            m = *reinterpret_cast<const float4*>(base + (j << 6));
        const float lf = __shfl_up_sync(FULL, m.w, 1);
        const float rg = __shfl_down_sync(FULL, m.x, 1);
        V[0] = (q == 0)  ? 0.f : lf;
        V[1] = m.x; V[2] = m.y; V[3] = m.z; V[4] = m.w;
        V[5] = (q == 15) ? 0.f : rg;
    };

    load_row(r0 - 1, W[0]);
    load_row(r0,     W[1]);

    float g[16];
    float gmn = 3.4e38f;
    float gmx = 0.0f;   // g >= 0

#pragma unroll
    for (int i = 0; i < 4; i++) {
        load_row(r0 + 1 + i, W[(i + 2) % 3]);
        const float* a = W[i % 3];           // top
        const float* b = W[(i + 1) % 3];     // mid
        const float* c = W[(i + 2) % 3];     // bot
#pragma unroll
        for (int p = 0; p < 4; p++) {
            const float a0 = a[p], a1 = a[p + 1], a2 = a[p + 2];
            const float b0 = b[p], b1 = b[p + 1], b2 = b[p + 2];
            const float c1 = c[p], c2 = c[p + 1], c3 = c[p + 2];
            // S = conv(wr + wr^T) = gx + gy
            float S = s00 * a0;
            S = fmaf(s11, b1, S);
            S = fmaf(s22, c3, S);
            S = fmaf(s01, a1 + b0, S);
            S = fmaf(s02, a2 + c1, S);
            S = fmaf(s12, b2 + c2, S);
            // D = conv(wr - wr^T) = gx - gy  (diagonal vanishes)
            float D = d01 * (a1 - b0);
            D = fmaf(d02, a2 - c1, D);
            D = fmaf(d12, b2 - c2, D);
            // |gx| + |gy| = max(|S|, |D|)
            const float gv = fmaxf(fabsf(S), fabsf(D));
            g[i * 4 + p] = gv;
            gmn = fminf(gmn, gv);
            gmx = fmaxf(gmx, gv);
        }
    }

    // --- block min/max reduction ---
#pragma unroll
    for (int o = 16; o; o >>= 1) {
        gmn = fminf(gmn, __shfl_xor_sync(FULL, gmn, o));
        gmx = fmaxf(gmx, __shfl_xor_sync(FULL, gmx, o));
    }
    if ((tid & 31) == 0) { smin[tid >> 5] = gmn; smax[tid >> 5] = gmx; }
    __syncthreads();
    gmn = smin[0]; gmx = smax[0];
#pragma unroll
    for (int i = 1; i < 8; i++) {
        gmn = fminf(gmn, smin[i]);
        gmx = fmaxf(gmx, smax[i]);
    }

    const float mul = 255.0f / fmaxf(gmx - gmn, 1.0f);
    const float isc = 1.0f / scale_p[0];

    // --- normalize + floor + scale; float4 stores ---
    float* __restrict__ op = out + (size_t)img * 4096 + (r0 << 6) + c0;
#pragma unroll
    for (int i = 0; i < 4; i++) {
        float4 o4;
        o4.x = floorf((g[i * 4 + 0] - gmn) * mul) * isc;
        o4.y = floorf((g[i * 4 + 1] - gmn) * mul) * isc;
        o4.z = floorf((g[i * 4 + 2] - gmn) * mul) * isc;
        o4.w = floorf((g[i * 4 + 3] - gmn) * mul) * isc;
        *reinterpret_cast<float4*>(op + (i << 6)) = o4;
    }
}

extern "C" void kernel_launch(void* const* d_in, const int* in_sizes, int n_in,
                              void* d_out, int out_size) {
    const float* in      = (const float*)d_in[0];  // (2048,1,64,64) fp32
    const float* w       = (const float*)d_in[1];  // (1,9) fp32
    const float* wf      = (const float*)d_in[2];  // (1,) fp32
    const float* scale_p = (const float*)d_in[3];  // (1,1) fp32
    float* out = (float*)d_out;                    // (1,2048,1,64,64) fp32
    (void)in_sizes; (void)n_in; (void)out_size;

    sobel_norm_kernel<<<NUM_IMG, 256>>>(in, w, wf, scale_p, out);
}